// round 14
// baseline (speedup 1.0000x reference)
#include <cuda_runtime.h>
#include <cuda_bf16.h>
#include <math.h>
#include <cstdint>

#define NN 512
#define CC 128
constexpr size_t RR = (size_t)NN * NN;
constexpr size_t RC = RR * CC;

// Scratch
__device__ __nv_bfloat16 g_xh[RC], g_xl[RC];        // layernormed x, [r][c]
__device__ __nv_bfloat16 g_ah[RC], g_al[RC];        // a, [c][i][k]
__device__ __nv_bfloat16 g_bh[RC], g_bl[RC];        // b, [c][j][k]
__device__ __nv_bfloat16 g_a2h[RC], g_a2l[RC];      // act2, [c][i][j]
__device__ float g_mean[RR], g_rstd[RR];

// Prepped weights ([n][k], bf16 hi/lo)
__device__ __nv_bfloat16 g_wph[256 * CC], g_wpl[256 * CC];
__device__ __nv_bfloat16 g_wgh[256 * CC];                  // gate hi only
__device__ __nv_bfloat16 g_w1h[CC * CC], g_w1l[CC * CC];   // cs ⊙ w_out ^T
__device__ __nv_bfloat16 g_w2h[CC * CC];                   // w_gate_out ^T hi only
__device__ float g_S1[CC], g_S2[CC];

__device__ __forceinline__ float sigm(float z) { return 1.0f / (1.0f + __expf(-z)); }
__device__ __forceinline__ void split_bf16(float v, unsigned short& h, unsigned short& l) {
    __nv_bfloat16 hb = __float2bfloat16(v);
    float rem = v - __bfloat162float(hb);
    h = __bfloat16_as_ushort(hb);
    l = __bfloat16_as_ushort(__float2bfloat16(rem));
}
__device__ __forceinline__ float bf2f(uint32_t u) {
    return __bfloat162float(__ushort_as_bfloat16((unsigned short)(u & 0xffffu)));
}
__device__ __forceinline__ uint32_t smem_u32(const void* p) {
    uint32_t a;
    asm("{ .reg .u64 t; cvta.to.shared.u64 t, %1; cvt.u32.u64 %0, t; }" : "=r"(a) : "l"(p));
    return a;
}
__device__ __forceinline__ void cp_async16(uint32_t dst, const void* src) {
    asm volatile("cp.async.cg.shared.global [%0], [%1], 16;" :: "r"(dst), "l"(src));
}
#define CP_COMMIT() asm volatile("cp.async.commit_group;" ::: "memory")
#define CP_WAIT1()  asm volatile("cp.async.wait_group 1;" ::: "memory")

__device__ __forceinline__ void ldsm4(uint32_t addr, uint32_t* r) {
    asm volatile("ldmatrix.sync.aligned.m8n8.x4.shared.b16 {%0,%1,%2,%3}, [%4];"
                 : "=r"(r[0]), "=r"(r[1]), "=r"(r[2]), "=r"(r[3]) : "r"(addr));
}
__device__ __forceinline__ void ldsm4t(uint32_t addr, uint32_t* r) {
    asm volatile("ldmatrix.sync.aligned.m8n8.x4.trans.shared.b16 {%0,%1,%2,%3}, [%4];"
                 : "=r"(r[0]), "=r"(r[1]), "=r"(r[2]), "=r"(r[3]) : "r"(addr));
}
__device__ __forceinline__ void mma16816(float* d, const uint32_t* a, const uint32_t* b) {
    asm volatile("mma.sync.aligned.m16n8k16.row.col.f32.bf16.bf16.f32 "
                 "{%0,%1,%2,%3}, {%4,%5,%6,%7}, {%8,%9}, {%0,%1,%2,%3};"
                 : "+f"(d[0]), "+f"(d[1]), "+f"(d[2]), "+f"(d[3])
                 : "r"(a[0]), "r"(a[1]), "r"(a[2]), "r"(a[3]), "r"(b[0]), "r"(b[1]));
}

// ---------------------------------------------------------------------------
__global__ void k_layernorm(const float* __restrict__ act,
                            const float* __restrict__ scale,
                            const float* __restrict__ offset) {
    int warp = threadIdx.x >> 5, lane = threadIdx.x & 31;
    size_t row = (size_t)blockIdx.x * 8 + warp;
    float4 v = ((const float4*)(act + row * CC))[lane];
    float s = v.x + v.y + v.z + v.w;
    float q = v.x * v.x + v.y * v.y + v.z * v.z + v.w * v.w;
#pragma unroll
    for (int o = 16; o; o >>= 1) {
        s += __shfl_xor_sync(0xffffffffu, s, o);
        q += __shfl_xor_sync(0xffffffffu, q, o);
    }
    float m = s * (1.0f / CC);
    float rs = rsqrtf(q * (1.0f / CC) - m * m + 1e-5f);
    float4 sc = ((const float4*)scale)[lane];
    float4 of = ((const float4*)offset)[lane];
    float o[4] = {(v.x - m) * rs * sc.x + of.x, (v.y - m) * rs * sc.y + of.y,
                  (v.z - m) * rs * sc.z + of.z, (v.w - m) * rs * sc.w + of.w};
    unsigned short hs[4], ls[4];
#pragma unroll
    for (int u = 0; u < 4; u++) split_bf16(o[u], hs[u], ls[u]);
    *(uint2*)(g_xh + row * CC + lane * 4) =
        make_uint2((uint32_t)hs[0] | ((uint32_t)hs[1] << 16), (uint32_t)hs[2] | ((uint32_t)hs[3] << 16));
    *(uint2*)(g_xl + row * CC + lane * 4) =
        make_uint2((uint32_t)ls[0] | ((uint32_t)ls[1] << 16), (uint32_t)ls[2] | ((uint32_t)ls[3] << 16));
}

// ---------------------------------------------------------------------------
__global__ void k_prep_pg(const float* __restrict__ wproj, const float* __restrict__ wgate) {
    int idx = blockIdx.x * 256 + threadIdx.x;
    int d = idx >> 7, c = idx & 127;
    unsigned short h, l;
    split_bf16(wproj[(size_t)c * 256 + d], h, l);
    g_wph[idx] = __ushort_as_bfloat16(h); g_wpl[idx] = __ushort_as_bfloat16(l);
    g_wgh[idx] = __float2bfloat16(wgate[(size_t)c * 256 + d]);
}
__global__ void k_prep_out(const float* __restrict__ wout, const float* __restrict__ wgo,
                           const float* __restrict__ cs) {
    int idx = blockIdx.x * 256 + threadIdx.x;
    int e = idx >> 7, c = idx & 127;
    unsigned short h, l;
    split_bf16(cs[c] * wout[(size_t)c * CC + e], h, l);
    g_w1h[idx] = __ushort_as_bfloat16(h); g_w1l[idx] = __ushort_as_bfloat16(l);
    g_w2h[idx] = __float2bfloat16(wgo[(size_t)c * CC + e]);
}
__global__ void k_prep_s(const float* __restrict__ wout,
                         const float* __restrict__ cs, const float* __restrict__ co) {
    int e = blockIdx.x, c = threadIdx.x;
    float w = wout[(size_t)c * CC + e];
    float s1 = cs[c] * w, s2 = co[c] * w;
    __shared__ float r1[4], r2[4];
#pragma unroll
    for (int o = 16; o; o >>= 1) {
        s1 += __shfl_xor_sync(0xffffffffu, s1, o);
        s2 += __shfl_xor_sync(0xffffffffu, s2, o);
    }
    if ((c & 31) == 0) { r1[c >> 5] = s1; r2[c >> 5] = s2; }
    __syncthreads();
    if (c == 0) {
        g_S1[e] = r1[0] + r1[1] + r1[2] + r1[3];
        g_S2[e] = r2[0] + r2[1] + r2[2] + r2[3];
    }
}

// ---------------------------------------------------------------------------
// K projgate: 256 threads, 4 CTAs/SM. 64r x 64d dual-GEMM, warps 2m x 4n,
// 2-stage pipeline, 64B-pitch XOR-swizzled tiles.
// Stage: xh, xl, wph, wpl, wgh (5 x 4096) = 20480.
// ---------------------------------------------------------------------------
#define PG_STAGE 20480
#define PG_SMEM  40960

__device__ __forceinline__ void pg_load(uint32_t sb, int kc, size_t rb, int db, int t) {
    int r = t >> 2, ch = t & 3;
    uint32_t off = r * 64 + ((ch ^ ((r >> 1) & 3)) << 4);
    cp_async16(sb + off, g_xh + (rb + r) * CC + kc + ch * 8);
    cp_async16(sb + 4096 + off, g_xl + (rb + r) * CC + kc + ch * 8);
    cp_async16(sb + 8192 + off, g_wph + (size_t)(db + r) * CC + kc + ch * 8);
    cp_async16(sb + 12288 + off, g_wpl + (size_t)(db + r) * CC + kc + ch * 8);
    cp_async16(sb + 16384 + off, g_wgh + (size_t)(db + r) * CC + kc + ch * 8);
}

__global__ void __launch_bounds__(256, 4) k_projgate_mma(const float* __restrict__ mask) {
    extern __shared__ char smem[];
    const uint32_t sbase = smem_u32(smem);
    const int t = threadIdx.x, lane = t & 31, wid = t >> 5;
    const int db = blockIdx.x * 64;
    const size_t rb = (size_t)blockIdx.y * 64;
    const int m0 = (wid >> 2) * 32, n0 = (wid & 3) * 16;

    float accP[2][2][4] = {}, accG[2][2][4] = {};

    const int rA = m0 + (lane & 15);
    const int sA = (rA >> 1) & 3;
    const int cA = lane >> 4;
    const int bRow = (lane & 7) + ((lane >> 4) << 3);
    const int rB = n0 + bRow;
    const int sB = (bRow >> 1) & 3;
    const int cB = (lane >> 3) & 1;

    pg_load(sbase, 0, rb, db, t);             CP_COMMIT();
    pg_load(sbase + PG_STAGE, 32, rb, db, t); CP_COMMIT();

    for (int kch = 0; kch < 4; kch++) {
        CP_WAIT1();
        __syncthreads();
        const uint32_t sb = sbase + (kch & 1) * PG_STAGE;
#pragma unroll
        for (int kk = 0; kk < 2; kk++) {
            const uint32_t aOff = (uint32_t)rA * 64 + (((cA ^ (kk << 1)) ^ sA) << 4);
            const uint32_t bOff = (uint32_t)rB * 64 + (((cB ^ (kk << 1)) ^ sB) << 4);
            uint32_t ah[2][4], al[2][4], b0[2][2], b1[2][2];
#pragma unroll
            for (int mi = 0; mi < 2; mi++) {
                ldsm4(sb + aOff + mi * 1024, ah[mi]);
                ldsm4(sb + 4096 + aOff + mi * 1024, al[mi]);
            }
            ldsm4(sb + 8192 + bOff, &b0[0][0]);
            ldsm4(sb + 12288 + bOff, &b1[0][0]);
#pragma unroll
            for (int ni = 0; ni < 2; ni++)
#pragma unroll
                for (int mi = 0; mi < 2; mi++) mma16816(accP[mi][ni], ah[mi], b0[ni]);
#pragma unroll
            for (int ni = 0; ni < 2; ni++)
#pragma unroll
                for (int mi = 0; mi < 2; mi++) mma16816(accP[mi][ni], al[mi], b0[ni]);
#pragma unroll
            for (int ni = 0; ni < 2; ni++)
#pragma unroll
                for (int mi = 0; mi < 2; mi++) mma16816(accP[mi][ni], ah[mi], b1[ni]);
            ldsm4(sb + 16384 + bOff, &b0[0][0]);
#pragma unroll
            for (int ni = 0; ni < 2; ni++)
#pragma unroll
                for (int mi = 0; mi < 2; mi++) mma16816(accG[mi][ni], ah[mi], b0[ni]);
#pragma unroll
            for (int ni = 0; ni < 2; ni++)
#pragma unroll
                for (int mi = 0; mi < 2; mi++) mma16816(accG[mi][ni], al[mi], b0[ni]);
        }
        __syncthreads();
        if (kch + 2 < 4) pg_load(sbase + (kch & 1) * PG_STAGE, (kch + 2) * 32, rb, db, t);
        CP_COMMIT();
    }

    // Epilogue: fused val -> smem transpose [d][68r] -> scatter
    float* buf = (float*)smem;
    const int mr = lane >> 2, ncq = lane & 3;
#pragma unroll
    for (int mi = 0; mi < 2; mi++) {
        int rl = m0 + mi * 16 + mr;
        float mk0 = __ldg(mask + rb + rl), mk8 = __ldg(mask + rb + rl + 8);
#pragma unroll
        for (int ni = 0; ni < 2; ni++) {
            int d0 = n0 + ni * 8 + ncq * 2;
            buf[d0 * 68 + rl]           = accP[mi][ni][0] * sigm(accG[mi][ni][0]) * mk0;
            buf[(d0 + 1) * 68 + rl]     = accP[mi][ni][1] * sigm(accG[mi][ni][1]) * mk0;
            buf[d0 * 68 + rl + 8]       = accP[mi][ni][2] * sigm(accG[mi][ni][2]) * mk8;
            buf[(d0 + 1) * 68 + rl + 8] = accP[mi][ni][3] * sigm(accG[mi][ni][3]) * mk8;
        }
    }
    __syncthreads();

    {
        int dl = t >> 2, rg = t & 3;
        int dg = db + dl, c = dg >> 1;
        __nv_bfloat16* dsth = (dg & 1) ? g_bh : g_ah;
        __nv_bfloat16* dstl = (dg & 1) ? g_bl : g_al;
        size_t base = (size_t)c * RR + rb + rg * 16;
#pragma unroll
        for (int i4 = 0; i4 < 2; i4++) {
            float4 va = *(float4*)&buf[dl * 68 + rg * 16 + i4 * 8];
            float4 vb = *(float4*)&buf[dl * 68 + rg * 16 + i4 * 8 + 4];
            float vv[8] = {va.x, va.y, va.z, va.w, vb.x, vb.y, vb.z, vb.w};
            unsigned short hs[8], ls[8];
#pragma unroll
            for (int j = 0; j < 8; j++) split_bf16(vv[j], hs[j], ls[j]);
            *(uint4*)(dsth + base + i4 * 8) =
                make_uint4((uint32_t)hs[0] | ((uint32_t)hs[1] << 16), (uint32_t)hs[2] | ((uint32_t)hs[3] << 16),
                           (uint32_t)hs[4] | ((uint32_t)hs[5] << 16), (uint32_t)hs[6] | ((uint32_t)hs[7] << 16));
            *(uint4*)(dstl + base + i4 * 8) =
                make_uint4((uint32_t)ls[0] | ((uint32_t)ls[1] << 16), (uint32_t)ls[2] | ((uint32_t)ls[3] << 16),
                           (uint32_t)ls[4] | ((uint32_t)ls[5] << 16), (uint32_t)ls[6] | ((uint32_t)ls[7] << 16));
        }
    }
}

// ---------------------------------------------------------------------------
// K pairmm: 256 threads, 4 CTAs/SM. 64i x 64j tiles, warps 2m x 4n,
// 3-stage pipeline, 64B-pitch swizzled tiles. (unchanged from R13)
// ---------------------------------------------------------------------------
#define PM_STAGE 16384
#define PM_SMEM  49152

__device__ __forceinline__ void pm_load(uint32_t sb, int kc, size_t cOff, int ib, int jb, int t) {
    int r = t >> 2, ch = t & 3;
    uint32_t off = r * 64 + ((ch ^ ((r >> 1) & 3)) << 4);
    cp_async16(sb + off, g_ah + cOff + (size_t)(ib + r) * NN + kc + ch * 8);
    cp_async16(sb + 4096 + off, g_al + cOff + (size_t)(ib + r) * NN + kc + ch * 8);
    cp_async16(sb + 8192 + off, g_bh + cOff + (size_t)(jb + r) * NN + kc + ch * 8);
    cp_async16(sb + 12288 + off, g_bl + cOff + (size_t)(jb + r) * NN + kc + ch * 8);
}

__global__ void __launch_bounds__(256, 4) k_pairmm_mma() {
    extern __shared__ char smem[];
    const uint32_t sbase = smem_u32(smem);
    const int t = threadIdx.x, lane = t & 31, wid = t >> 5;
    const int c = blockIdx.z;
    const int ib = blockIdx.y * 64, jb = blockIdx.x * 64;
    const size_t cOff = (size_t)c * RR;
    const int m0 = (wid >> 2) * 32, n0 = (wid & 3) * 16;

    float acc[2][2][4] = {};

    const int rA = m0 + (lane & 15);
    const int sA = (rA >> 1) & 3;
    const int cA = lane >> 4;
    const int bRow = (lane & 7) + ((lane >> 4) << 3);
    const int rB = n0 + bRow;
    const int sB = (bRow >> 1) & 3;
    const int cB = (lane >> 3) & 1;

    pm_load(sbase, 0, cOff, ib, jb, t);             CP_COMMIT();
    pm_load(sbase + PM_STAGE, 32, cOff, ib, jb, t); CP_COMMIT();

    for (int kch = 0; kch < 16; kch++) {
        CP_WAIT1();
        __syncthreads();
        if (kch + 2 < 16)
            pm_load(sbase + ((kch + 2) % 3) * PM_STAGE, (kch + 2) * 32, cOff, ib, jb, t);
        CP_COMMIT();
        const uint32_t sb = sbase + (kch % 3) * PM_STAGE;
#pragma unroll
        for (int kk = 0; kk < 2; kk++) {
            const uint32_t aOff = (uint32_t)rA * 64 + (((cA ^ (kk << 1)) ^ sA) << 4);
            const uint32_t bOff = (uint32_t)rB * 64 + (((cB ^ (kk << 1)) ^ sB) << 4);
            uint32_t ah[2][4], al[2][4], bh[2][2], bl[2][2];
#pragma unroll
            for (int mi = 0; mi < 2; mi++) {
                ldsm4(sb + aOff + mi * 1024, ah[mi]);
                ldsm4(sb + 4096 + aOff + mi * 1024, al[mi]);
            }
            ldsm4(sb + 8192 + bOff, &bh[0][0]);
            ldsm4(sb + 12288 + bOff, &bl[0][0]);
#pragma unroll
            for (int ni = 0; ni < 2; ni++)
#pragma unroll
                for (int mi = 0; mi < 2; mi++) mma16816(acc[mi][ni], ah[mi], bh[ni]);
#pragma unroll
            for (int ni = 0; ni < 2; ni++)
#pragma unroll
                for (int mi = 0; mi < 2; mi++) mma16816(acc[mi][ni], al[mi], bh[ni]);
#pragma unroll
            for (int ni = 0; ni < 2; ni++)
#pragma unroll
                for (int mi = 0; mi < 2; mi++) mma16816(acc[mi][ni], ah[mi], bl[ni]);
        }
    }

    const int mr = lane >> 2, nc = (lane & 3) * 2;
#pragma unroll
    for (int mi = 0; mi < 2; mi++)
#pragma unroll
        for (int ni = 0; ni < 2; ni++) {
            size_t pos0 = cOff + (size_t)(ib + m0 + mi * 16 + mr) * NN + jb + n0 + ni * 8 + nc;
            size_t pos8 = pos0 + (size_t)8 * NN;
            unsigned short h0, l0, h1, l1;
            split_bf16(acc[mi][ni][0], h0, l0); split_bf16(acc[mi][ni][1], h1, l1);
            *(uint32_t*)(g_a2h + pos0) = (uint32_t)h0 | ((uint32_t)h1 << 16);
            *(uint32_t*)(g_a2l + pos0) = (uint32_t)l0 | ((uint32_t)l1 << 16);
            split_bf16(acc[mi][ni][2], h0, l0); split_bf16(acc[mi][ni][3], h1, l1);
            *(uint32_t*)(g_a2h + pos8) = (uint32_t)h0 | ((uint32_t)h1 << 16);
            *(uint32_t*)(g_a2l + pos8) = (uint32_t)l0 | ((uint32_t)l1 << 16);
        }
}

// ---------------------------------------------------------------------------
__global__ void k_cstats() {
    size_t r0 = ((size_t)blockIdx.x * 256 + threadIdx.x) * 4;
    float s[4] = {}, q[4] = {};
#pragma unroll 4
    for (int c = 0; c < CC; c++) {
        uint2 hv = *(const uint2*)(g_a2h + (size_t)c * RR + r0);
        uint2 lv = *(const uint2*)(g_a2l + (size_t)c * RR + r0);
        float v[4] = {bf2f(hv.x) + bf2f(lv.x), bf2f(hv.x >> 16) + bf2f(lv.x >> 16),
                      bf2f(hv.y) + bf2f(lv.y), bf2f(hv.y >> 16) + bf2f(lv.y >> 16)};
#pragma unroll
        for (int j = 0; j < 4; j++) { s[j] += v[j]; q[j] += v[j] * v[j]; }
    }
    float4 mo, ro;
    float* mp = &mo.x; float* rp = &ro.x;
#pragma unroll
    for (int j = 0; j < 4; j++) {
        float m = s[j] * (1.0f / CC);
        mp[j] = m;
        rp[j] = rsqrtf(q[j] * (1.0f / CC) - m * m + 1e-5f);
    }
    *(float4*)(g_mean + r0) = mo;
    *(float4*)(g_rstd + r0) = ro;
}

// ---------------------------------------------------------------------------
// K final: 256 threads, 3 CTAs/SM. 64r x 64e dual GEMM, warps 2m x 4n,
// 2-stage. Gate GEMM hi-only weights. (unchanged from R12)
// ---------------------------------------------------------------------------
#define FN_STAGE 34816
#define FN_SMEM  69632

__device__ __forceinline__ void fn_load(uint32_t sb, int kc, size_t rb, int eb, int t) {
    {
        int cc2 = t >> 3, ch = t & 7;
        cp_async16(sb + cc2 * 144 + ch * 16, g_a2h + (size_t)(kc + cc2) * RR + rb + ch * 8);
        cp_async16(sb + 4608 + cc2 * 144 + ch * 16, g_a2l + (size_t)(kc + cc2) * RR + rb + ch * 8);
    }
    int r = t >> 2, ch = t & 3;
    cp_async16(sb + 9216 + r * 80 + ch * 16, g_xh + (rb + r) * CC + kc + ch * 8);
    cp_async16(sb + 14336 + r * 80 + ch * 16, g_xl + (rb + r) * CC + kc + ch * 8);
    cp_async16(sb + 19456 + r * 80 + ch * 16, g_w1h + (size_t)(eb + r) * CC + kc + ch * 8);
    cp_async16(sb + 24576 + r * 80 + ch * 16, g_w1l + (size_t)(eb + r) * CC + kc + ch * 8);
    cp_async16(sb + 29696 + r * 80 + ch * 16, g_w2h + (size_t)(eb + r) * CC + kc + ch * 8);
}

__global__ void __launch_bounds__(256, 3) k_final_mma(const float* __restrict__ bout,
                                                      const float* __restrict__ bgo,
                                                      float* __restrict__ out) {
    extern __shared__ char smem[];
    const uint32_t sbase = smem_u32(smem);
    const int t = threadIdx.x, lane = t & 31, wid = t >> 5;
    const int eb = blockIdx.x * 64;
    const size_t rb = (size_t)blockIdx.y * 64;
    const int m0 = (wid >> 2) * 32, n0 = (wid & 3) * 16;

    float accO[2][2][4] = {}, accG[2][2][4] = {};

    const int crow = (lane & 7) + ((lane >> 4) & 1) * 8;
    const int r8 = ((lane >> 3) & 1) * 8;
    const int bRow = (lane & 7) + ((lane >> 4) << 3);
    const int bK16 = ((lane >> 3) & 1) * 16;

    fn_load(sbase, 0, rb, eb, t);             CP_COMMIT();
    fn_load(sbase + FN_STAGE, 32, rb, eb, t); CP_COMMIT();

    for (int kch = 0; kch < 4; kch++) {
        CP_WAIT1();
        __syncthreads();
        const uint32_t st = sbase + (kch & 1) * FN_STAGE;
        const uint32_t aX = st + 9216 + (m0 + (lane & 15)) * 80 + (lane >> 4) * 16;
        const uint32_t w1B = st + 19456 + (n0 + bRow) * 80 + bK16;
#pragma unroll
        for (int kk = 0; kk < 2; kk++) {
            const uint32_t ko = kk * 32;
            {
                uint32_t a1h[2][4], a1l[2][4], b1h[2][2], b1l[2][2];
                const uint32_t aT = st + (kk * 16 + crow) * 144 + (m0 + r8) * 2;
#pragma unroll
                for (int mi = 0; mi < 2; mi++) {
                    ldsm4t(aT + mi * 32, a1h[mi]);
                    ldsm4t(aT + mi * 32 + 4608, a1l[mi]);
                }
                ldsm4(w1B + ko, &b1h[0][0]);
                ldsm4(w1B + ko + 5120, &b1l[0][0]);
#pragma unroll
                for (int ni = 0; ni < 2; ni++)
#pragma unroll
                    for (int mi = 0; mi < 2; mi++) mma16816(accO[mi][ni], a1h[mi], b1h[ni]);
#pragma unroll
                for (int ni = 0; ni < 2; ni++)
#pragma unroll
                    for (int mi = 0; mi < 2; mi++) mma16816(accO[mi][ni], a1l[mi], b1h[ni]);
#pragma unroll
                for (int ni = 0; ni < 2; ni++)
#pragma unroll
                    for (int mi = 0; mi < 2; mi++) mma16816(accO[mi][ni], a1h[mi], b1l[ni]);
            }
            {
                uint32_t a2h[2][4], a2l[2][4], b2h[2][2];
#pragma unroll
                for (int mi = 0; mi < 2; mi++) {
                    ldsm4(aX + mi * 1280 + ko, a2h[mi]);
                    ldsm4(aX + mi * 1280 + ko + 5120, a2l[mi]);
                }
                ldsm4(w1B + ko + 10240, &b2h[0][0]);
#pragma unroll
                for (int ni = 0; ni < 2; ni++)
#pragma unroll
                    for (int mi = 0; mi < 2; mi++) mma16816(accG[mi][ni], a2h[mi], b2h[ni]);
#pragma unroll
                for (int ni = 0; ni < 2; ni++)
#pragma unroll
                    for (int mi = 0; mi < 2; mi++) mma16816(accG[mi][ni], a2l[mi], b2h[ni]);
            }
        }
        __syncthreads();
        if (kch + 2 < 4) fn_load(sbase + (kch & 1) * FN_STAGE, (kch + 2) * 32, rb, eb, t);
        CP_COMMIT();
    }

    const int mr = lane >> 2, ncl = (lane & 3) * 2;
    float mm[2][2], rs[2][2];
#pragma unroll
    for (int mi = 0; mi < 2; mi++)
#pragma unroll
        for (int half = 0; half < 2; half++) {
            size_t r = rb + m0 + mi * 16 + mr + half * 8;
            mm[mi][half] = g_mean[r];
            rs[mi][half] = g_rstd[r];
        }
#pragma unroll
    for (int ni = 0; ni < 2; ni++) {
        int e0 = eb + n0 + ni * 8 + ncl;
        float s1a = g_S1[e0], s1b = g_S1[e0 + 1];
        float s2a = g_S2[e0], s2b = g_S2[e0 + 1];
        float boa = __ldg(bout + e0), bob = __ldg(bout + e0 + 1);
        float bga = __ldg(bgo + e0), bgb = __ldg(bgo + e0 + 1);
#pragma unroll
        for (int mi = 0; mi < 2; mi++)
#pragma unroll
            for (int half = 0; half < 2; half++) {
                size_t r = rb + m0 + mi * 16 + mr + half * 8;
                float p0 = accO[mi][ni][half * 2], p1 = accO[mi][ni][half * 2 + 1];
                float q0 = accG[mi][ni][half * 2], q1 = accG[mi][ni][half * 2 + 1];
                float o0 = (rs[mi][half] * (p0 - mm[mi][half] * s1a) + s2a + boa) * sigm(q0 + bga);
                float o1 = (rs[mi][half] * (p1 - mm[mi][half] * s1b) + s2b + bob) * sigm(q1 + bgb);
                *(float2*)(out + r * CC + e0) = make_float2(o0, o1);
            }
    }
}

// ---------------------------------------------------------------------------
extern "C" void kernel_launch(void* const* d_in, const int* in_sizes, int n_in,
                              void* d_out, int out_size) {
    const float* act   = (const float*)d_in[0];
    const float* mask  = (const float*)d_in[1];
    const float* ln_s  = (const float*)d_in[2];
    const float* ln_o  = (const float*)d_in[3];
    const float* wproj = (const float*)d_in[4];
    const float* wgate = (const float*)d_in[5];
    const float* cn_s  = (const float*)d_in[6];
    const float* cn_o  = (const float*)d_in[7];
    const float* wout  = (const float*)d_in[8];
    const float* bout  = (const float*)d_in[9];
    const float* wgo   = (const float*)d_in[10];
    const float* bgo   = (const float*)d_in[11];
    float* out = (float*)d_out;

    cudaFuncSetAttribute(k_projgate_mma, cudaFuncAttributeMaxDynamicSharedMemorySize, PG_SMEM);
    cudaFuncSetAttribute(k_pairmm_mma, cudaFuncAttributeMaxDynamicSharedMemorySize, PM_SMEM);
    cudaFuncSetAttribute(k_final_mma, cudaFuncAttributeMaxDynamicSharedMemorySize, FN_SMEM);

    k_prep_pg<<<128, 256>>>(wproj, wgate);                                  // 1
    k_prep_out<<<64, 256>>>(wout, wgo, cn_s);                               // 2
    k_layernorm<<<(int)(RR / 8), 256>>>(act, ln_s, ln_o);                   // 3
    k_projgate_mma<<<dim3(4, 4096), 256, PG_SMEM>>>(mask);                  // 4 <- profiled
    k_pairmm_mma<<<dim3(8, 8, 128), 256, PM_SMEM>>>();                      // 5
    k_prep_s<<<128, 128>>>(wout, cn_s, cn_o);                               // 6
    k_cstats<<<256, 256>>>();                                               // 7
    k_final_mma<<<dim3(2, 4096), 256, FN_SMEM>>>(bout, bgo, out);           // 8
}

// round 15
// speedup vs baseline: 1.0489x; 1.0489x over previous
#include <cuda_runtime.h>
#include <cuda_bf16.h>
#include <math.h>
#include <cstdint>

#define NN 512
#define CC 128
constexpr size_t RR = (size_t)NN * NN;
constexpr size_t RC = RR * CC;

__device__ __nv_bfloat16 g_xh[RC], g_xl[RC];
__device__ __nv_bfloat16 g_ah[RC], g_al[RC];
__device__ __nv_bfloat16 g_bh[RC], g_bl[RC];
__device__ __nv_bfloat16 g_a2h[RC], g_a2l[RC];
__device__ float g_mean[RR], g_rstd[RR];

__device__ __nv_bfloat16 g_wph[256 * CC], g_wpl[256 * CC];
__device__ __nv_bfloat16 g_wgh[256 * CC];
__device__ __nv_bfloat16 g_w1h[CC * CC], g_w1l[CC * CC];
__device__ __nv_bfloat16 g_w2h[CC * CC];
__device__ float g_S1[CC], g_S2[CC];

__device__ __forceinline__ float sigm(float z) { return 1.0f / (1.0f + __expf(-z)); }
__device__ __forceinline__ void split_bf16(float v, unsigned short& h, unsigned short& l) {
    __nv_bfloat16 hb = __float2bfloat16(v);
    float rem = v - __bfloat162float(hb);
    h = __bfloat16_as_ushort(hb);
    l = __bfloat16_as_ushort(__float2bfloat16(rem));
}
__device__ __forceinline__ float bf2f(uint32_t u) {
    return __bfloat162float(__ushort_as_bfloat16((unsigned short)(u & 0xffffu)));
}
__device__ __forceinline__ uint32_t smem_u32(const void* p) {
    uint32_t a;
    asm("{ .reg .u64 t; cvta.to.shared.u64 t, %1; cvt.u32.u64 %0, t; }" : "=r"(a) : "l"(p));
    return a;
}
__device__ __forceinline__ void cp_async16(uint32_t dst, const void* src) {
    asm volatile("cp.async.cg.shared.global [%0], [%1], 16;" :: "r"(dst), "l"(src));
}
#define CP_COMMIT() asm volatile("cp.async.commit_group;" ::: "memory")
#define CP_WAIT1()  asm volatile("cp.async.wait_group 1;" ::: "memory")

__device__ __forceinline__ void ldsm4(uint32_t addr, uint32_t* r) {
    asm volatile("ldmatrix.sync.aligned.m8n8.x4.shared.b16 {%0,%1,%2,%3}, [%4];"
                 : "=r"(r[0]), "=r"(r[1]), "=r"(r[2]), "=r"(r[3]) : "r"(addr));
}
__device__ __forceinline__ void ldsm4t(uint32_t addr, uint32_t* r) {
    asm volatile("ldmatrix.sync.aligned.m8n8.x4.trans.shared.b16 {%0,%1,%2,%3}, [%4];"
                 : "=r"(r[0]), "=r"(r[1]), "=r"(r[2]), "=r"(r[3]) : "r"(addr));
}
__device__ __forceinline__ void mma16816(float* d, const uint32_t* a, const uint32_t* b) {
    asm volatile("mma.sync.aligned.m16n8k16.row.col.f32.bf16.bf16.f32 "
                 "{%0,%1,%2,%3}, {%4,%5,%6,%7}, {%8,%9}, {%0,%1,%2,%3};"
                 : "+f"(d[0]), "+f"(d[1]), "+f"(d[2]), "+f"(d[3])
                 : "r"(a[0]), "r"(a[1]), "r"(a[2]), "r"(a[3]), "r"(b[0]), "r"(b[1]));
}

// ---------------------------------------------------------------------------
__global__ void k_layernorm(const float* __restrict__ act,
                            const float* __restrict__ scale,
                            const float* __restrict__ offset) {
    int warp = threadIdx.x >> 5, lane = threadIdx.x & 31;
    size_t row = (size_t)blockIdx.x * 8 + warp;
    float4 v = ((const float4*)(act + row * CC))[lane];
    float s = v.x + v.y + v.z + v.w;
    float q = v.x * v.x + v.y * v.y + v.z * v.z + v.w * v.w;
#pragma unroll
    for (int o = 16; o; o >>= 1) {
        s += __shfl_xor_sync(0xffffffffu, s, o);
        q += __shfl_xor_sync(0xffffffffu, q, o);
    }
    float m = s * (1.0f / CC);
    float rs = rsqrtf(q * (1.0f / CC) - m * m + 1e-5f);
    float4 sc = ((const float4*)scale)[lane];
    float4 of = ((const float4*)offset)[lane];
    float o[4] = {(v.x - m) * rs * sc.x + of.x, (v.y - m) * rs * sc.y + of.y,
                  (v.z - m) * rs * sc.z + of.z, (v.w - m) * rs * sc.w + of.w};
    unsigned short hs[4], ls[4];
#pragma unroll
    for (int u = 0; u < 4; u++) split_bf16(o[u], hs[u], ls[u]);
    *(uint2*)(g_xh + row * CC + lane * 4) =
        make_uint2((uint32_t)hs[0] | ((uint32_t)hs[1] << 16), (uint32_t)hs[2] | ((uint32_t)hs[3] << 16));
    *(uint2*)(g_xl + row * CC + lane * 4) =
        make_uint2((uint32_t)ls[0] | ((uint32_t)ls[1] << 16), (uint32_t)ls[2] | ((uint32_t)ls[3] << 16));
}

// ---------------------------------------------------------------------------
__global__ void k_prep_pg(const float* __restrict__ wproj, const float* __restrict__ wgate) {
    int idx = blockIdx.x * 256 + threadIdx.x;
    int d = idx >> 7, c = idx & 127;
    unsigned short h, l;
    split_bf16(wproj[(size_t)c * 256 + d], h, l);
    g_wph[idx] = __ushort_as_bfloat16(h); g_wpl[idx] = __ushort_as_bfloat16(l);
    g_wgh[idx] = __float2bfloat16(wgate[(size_t)c * 256 + d]);
}
__global__ void k_prep_out(const float* __restrict__ wout, const float* __restrict__ wgo,
                           const float* __restrict__ cs) {
    int idx = blockIdx.x * 256 + threadIdx.x;
    int e = idx >> 7, c = idx & 127;
    unsigned short h, l;
    split_bf16(cs[c] * wout[(size_t)c * CC + e], h, l);
    g_w1h[idx] = __ushort_as_bfloat16(h); g_w1l[idx] = __ushort_as_bfloat16(l);
    g_w2h[idx] = __float2bfloat16(wgo[(size_t)c * CC + e]);
}
__global__ void k_prep_s(const float* __restrict__ wout,
                         const float* __restrict__ cs, const float* __restrict__ co) {
    int e = blockIdx.x, c = threadIdx.x;
    float w = wout[(size_t)c * CC + e];
    float s1 = cs[c] * w, s2 = co[c] * w;
    __shared__ float r1[4], r2[4];
#pragma unroll
    for (int o = 16; o; o >>= 1) {
        s1 += __shfl_xor_sync(0xffffffffu, s1, o);
        s2 += __shfl_xor_sync(0xffffffffu, s2, o);
    }
    if ((c & 31) == 0) { r1[c >> 5] = s1; r2[c >> 5] = s2; }
    __syncthreads();
    if (c == 0) {
        g_S1[e] = r1[0] + r1[1] + r1[2] + r1[3];
        g_S2[e] = r2[0] + r2[1] + r2[2] + r2[3];
    }
}

// ---------------------------------------------------------------------------
// K projgate: R13 config (3-stage, 3 CTAs/SM, swizzled 64B tiles).
// ---------------------------------------------------------------------------
#define PG_STAGE 20480
#define PG_SMEM  61440

__device__ __forceinline__ void pg_load(uint32_t sb, int kc, size_t rb, int db, int t) {
    int r = t >> 2, ch = t & 3;
    uint32_t off = r * 64 + ((ch ^ ((r >> 1) & 3)) << 4);
    cp_async16(sb + off, g_xh + (rb + r) * CC + kc + ch * 8);
    cp_async16(sb + 4096 + off, g_xl + (rb + r) * CC + kc + ch * 8);
    cp_async16(sb + 8192 + off, g_wph + (size_t)(db + r) * CC + kc + ch * 8);
    cp_async16(sb + 12288 + off, g_wpl + (size_t)(db + r) * CC + kc + ch * 8);
    cp_async16(sb + 16384 + off, g_wgh + (size_t)(db + r) * CC + kc + ch * 8);
}

__global__ void __launch_bounds__(256, 3) k_projgate_mma(const float* __restrict__ mask) {
    extern __shared__ char smem[];
    const uint32_t sbase = smem_u32(smem);
    const int t = threadIdx.x, lane = t & 31, wid = t >> 5;
    const int db = blockIdx.x * 64;
    const size_t rb = (size_t)blockIdx.y * 64;
    const int m0 = (wid >> 2) * 32, n0 = (wid & 3) * 16;

    float accP[2][2][4] = {}, accG[2][2][4] = {};

    const int rA = m0 + (lane & 15);
    const int sA = (rA >> 1) & 3;
    const int cA = lane >> 4;
    const int bRow = (lane & 7) + ((lane >> 4) << 3);
    const int rB = n0 + bRow;
    const int sB = (bRow >> 1) & 3;
    const int cB = (lane >> 3) & 1;

    pg_load(sbase, 0, rb, db, t);             CP_COMMIT();
    pg_load(sbase + PG_STAGE, 32, rb, db, t); CP_COMMIT();

    for (int kch = 0; kch < 4; kch++) {
        CP_WAIT1();
        __syncthreads();
        if (kch + 2 < 4)
            pg_load(sbase + ((kch + 2) % 3) * PG_STAGE, (kch + 2) * 32, rb, db, t);
        CP_COMMIT();
        const uint32_t sb = sbase + (kch % 3) * PG_STAGE;
#pragma unroll
        for (int kk = 0; kk < 2; kk++) {
            const uint32_t aOff = (uint32_t)rA * 64 + (((cA ^ (kk << 1)) ^ sA) << 4);
            const uint32_t bOff = (uint32_t)rB * 64 + (((cB ^ (kk << 1)) ^ sB) << 4);
            uint32_t ah[2][4], al[2][4], b0[2][2], b1[2][2];
#pragma unroll
            for (int mi = 0; mi < 2; mi++) {
                ldsm4(sb + aOff + mi * 1024, ah[mi]);
                ldsm4(sb + 4096 + aOff + mi * 1024, al[mi]);
            }
            ldsm4(sb + 8192 + bOff, &b0[0][0]);
            ldsm4(sb + 12288 + bOff, &b1[0][0]);
#pragma unroll
            for (int ni = 0; ni < 2; ni++)
#pragma unroll
                for (int mi = 0; mi < 2; mi++) mma16816(accP[mi][ni], ah[mi], b0[ni]);
#pragma unroll
            for (int ni = 0; ni < 2; ni++)
#pragma unroll
                for (int mi = 0; mi < 2; mi++) mma16816(accP[mi][ni], al[mi], b0[ni]);
#pragma unroll
            for (int ni = 0; ni < 2; ni++)
#pragma unroll
                for (int mi = 0; mi < 2; mi++) mma16816(accP[mi][ni], ah[mi], b1[ni]);
            ldsm4(sb + 16384 + bOff, &b0[0][0]);
#pragma unroll
            for (int ni = 0; ni < 2; ni++)
#pragma unroll
                for (int mi = 0; mi < 2; mi++) mma16816(accG[mi][ni], ah[mi], b0[ni]);
#pragma unroll
            for (int ni = 0; ni < 2; ni++)
#pragma unroll
                for (int mi = 0; mi < 2; mi++) mma16816(accG[mi][ni], al[mi], b0[ni]);
        }
    }
    __syncthreads();

    float* buf = (float*)smem;
    const int mr = lane >> 2, ncq = lane & 3;
#pragma unroll
    for (int mi = 0; mi < 2; mi++) {
        int rl = m0 + mi * 16 + mr;
        float mk0 = __ldg(mask + rb + rl), mk8 = __ldg(mask + rb + rl + 8);
#pragma unroll
        for (int ni = 0; ni < 2; ni++) {
            int d0 = n0 + ni * 8 + ncq * 2;
            buf[d0 * 68 + rl]           = accP[mi][ni][0] * sigm(accG[mi][ni][0]) * mk0;
            buf[(d0 + 1) * 68 + rl]     = accP[mi][ni][1] * sigm(accG[mi][ni][1]) * mk0;
            buf[d0 * 68 + rl + 8]       = accP[mi][ni][2] * sigm(accG[mi][ni][2]) * mk8;
            buf[(d0 + 1) * 68 + rl + 8] = accP[mi][ni][3] * sigm(accG[mi][ni][3]) * mk8;
        }
    }
    __syncthreads();

    {
        int dl = t >> 2, rg = t & 3;
        int dg = db + dl, c = dg >> 1;
        __nv_bfloat16* dsth = (dg & 1) ? g_bh : g_ah;
        __nv_bfloat16* dstl = (dg & 1) ? g_bl : g_al;
        size_t base = (size_t)c * RR + rb + rg * 16;
#pragma unroll
        for (int i4 = 0; i4 < 2; i4++) {
            float4 va = *(float4*)&buf[dl * 68 + rg * 16 + i4 * 8];
            float4 vb = *(float4*)&buf[dl * 68 + rg * 16 + i4 * 8 + 4];
            float vv[8] = {va.x, va.y, va.z, va.w, vb.x, vb.y, vb.z, vb.w};
            unsigned short hs[8], ls[8];
#pragma unroll
            for (int j = 0; j < 8; j++) split_bf16(vv[j], hs[j], ls[j]);
            *(uint4*)(dsth + base + i4 * 8) =
                make_uint4((uint32_t)hs[0] | ((uint32_t)hs[1] << 16), (uint32_t)hs[2] | ((uint32_t)hs[3] << 16),
                           (uint32_t)hs[4] | ((uint32_t)hs[5] << 16), (uint32_t)hs[6] | ((uint32_t)hs[7] << 16));
            *(uint4*)(dstl + base + i4 * 8) =
                make_uint4((uint32_t)ls[0] | ((uint32_t)ls[1] << 16), (uint32_t)ls[2] | ((uint32_t)ls[3] << 16),
                           (uint32_t)ls[4] | ((uint32_t)ls[5] << 16), (uint32_t)ls[6] | ((uint32_t)ls[7] << 16));
        }
    }
}

// ---------------------------------------------------------------------------
// K pairmm: unchanged R13 (3-stage, 4 CTAs/SM, swizzled).
// ---------------------------------------------------------------------------
#define PM_STAGE 16384
#define PM_SMEM  49152

__device__ __forceinline__ void pm_load(uint32_t sb, int kc, size_t cOff, int ib, int jb, int t) {
    int r = t >> 2, ch = t & 3;
    uint32_t off = r * 64 + ((ch ^ ((r >> 1) & 3)) << 4);
    cp_async16(sb + off, g_ah + cOff + (size_t)(ib + r) * NN + kc + ch * 8);
    cp_async16(sb + 4096 + off, g_al + cOff + (size_t)(ib + r) * NN + kc + ch * 8);
    cp_async16(sb + 8192 + off, g_bh + cOff + (size_t)(jb + r) * NN + kc + ch * 8);
    cp_async16(sb + 12288 + off, g_bl + cOff + (size_t)(jb + r) * NN + kc + ch * 8);
}

__global__ void __launch_bounds__(256, 4) k_pairmm_mma() {
    extern __shared__ char smem[];
    const uint32_t sbase = smem_u32(smem);
    const int t = threadIdx.x, lane = t & 31, wid = t >> 5;
    const int c = blockIdx.z;
    const int ib = blockIdx.y * 64, jb = blockIdx.x * 64;
    const size_t cOff = (size_t)c * RR;
    const int m0 = (wid >> 2) * 32, n0 = (wid & 3) * 16;

    float acc[2][2][4] = {};

    const int rA = m0 + (lane & 15);
    const int sA = (rA >> 1) & 3;
    const int cA = lane >> 4;
    const int bRow = (lane & 7) + ((lane >> 4) << 3);
    const int rB = n0 + bRow;
    const int sB = (bRow >> 1) & 3;
    const int cB = (lane >> 3) & 1;

    pm_load(sbase, 0, cOff, ib, jb, t);             CP_COMMIT();
    pm_load(sbase + PM_STAGE, 32, cOff, ib, jb, t); CP_COMMIT();

    for (int kch = 0; kch < 16; kch++) {
        CP_WAIT1();
        __syncthreads();
        if (kch + 2 < 16)
            pm_load(sbase + ((kch + 2) % 3) * PM_STAGE, (kch + 2) * 32, cOff, ib, jb, t);
        CP_COMMIT();
        const uint32_t sb = sbase + (kch % 3) * PM_STAGE;
#pragma unroll
        for (int kk = 0; kk < 2; kk++) {
            const uint32_t aOff = (uint32_t)rA * 64 + (((cA ^ (kk << 1)) ^ sA) << 4);
            const uint32_t bOff = (uint32_t)rB * 64 + (((cB ^ (kk << 1)) ^ sB) << 4);
            uint32_t ah[2][4], al[2][4], bh[2][2], bl[2][2];
#pragma unroll
            for (int mi = 0; mi < 2; mi++) {
                ldsm4(sb + aOff + mi * 1024, ah[mi]);
                ldsm4(sb + 4096 + aOff + mi * 1024, al[mi]);
            }
            ldsm4(sb + 8192 + bOff, &bh[0][0]);
            ldsm4(sb + 12288 + bOff, &bl[0][0]);
#pragma unroll
            for (int ni = 0; ni < 2; ni++)
#pragma unroll
                for (int mi = 0; mi < 2; mi++) mma16816(acc[mi][ni], ah[mi], bh[ni]);
#pragma unroll
            for (int ni = 0; ni < 2; ni++)
#pragma unroll
                for (int mi = 0; mi < 2; mi++) mma16816(acc[mi][ni], al[mi], bh[ni]);
#pragma unroll
            for (int ni = 0; ni < 2; ni++)
#pragma unroll
                for (int mi = 0; mi < 2; mi++) mma16816(acc[mi][ni], ah[mi], bl[ni]);
        }
    }

    const int mr = lane >> 2, nc = (lane & 3) * 2;
#pragma unroll
    for (int mi = 0; mi < 2; mi++)
#pragma unroll
        for (int ni = 0; ni < 2; ni++) {
            size_t pos0 = cOff + (size_t)(ib + m0 + mi * 16 + mr) * NN + jb + n0 + ni * 8 + nc;
            size_t pos8 = pos0 + (size_t)8 * NN;
            unsigned short h0, l0, h1, l1;
            split_bf16(acc[mi][ni][0], h0, l0); split_bf16(acc[mi][ni][1], h1, l1);
            *(uint32_t*)(g_a2h + pos0) = (uint32_t)h0 | ((uint32_t)h1 << 16);
            *(uint32_t*)(g_a2l + pos0) = (uint32_t)l0 | ((uint32_t)l1 << 16);
            split_bf16(acc[mi][ni][2], h0, l0); split_bf16(acc[mi][ni][3], h1, l1);
            *(uint32_t*)(g_a2h + pos8) = (uint32_t)h0 | ((uint32_t)h1 << 16);
            *(uint32_t*)(g_a2l + pos8) = (uint32_t)l0 | ((uint32_t)l1 << 16);
        }
}

// ---------------------------------------------------------------------------
__global__ void k_cstats() {
    size_t r0 = ((size_t)blockIdx.x * 256 + threadIdx.x) * 4;
    float s[4] = {}, q[4] = {};
#pragma unroll 4
    for (int c = 0; c < CC; c++) {
        uint2 hv = *(const uint2*)(g_a2h + (size_t)c * RR + r0);
        uint2 lv = *(const uint2*)(g_a2l + (size_t)c * RR + r0);
        float v[4] = {bf2f(hv.x) + bf2f(lv.x), bf2f(hv.x >> 16) + bf2f(lv.x >> 16),
                      bf2f(hv.y) + bf2f(lv.y), bf2f(hv.y >> 16) + bf2f(lv.y >> 16)};
#pragma unroll
        for (int j = 0; j < 4; j++) { s[j] += v[j]; q[j] += v[j] * v[j]; }
    }
    float4 mo, ro;
    float* mp = &mo.x; float* rp = &ro.x;
#pragma unroll
    for (int j = 0; j < 4; j++) {
        float m = s[j] * (1.0f / CC);
        mp[j] = m;
        rp[j] = rsqrtf(q[j] * (1.0f / CC) - m * m + 1e-5f);
    }
    *(float4*)(g_mean + r0) = mo;
    *(float4*)(g_rstd + r0) = ro;
}

// ---------------------------------------------------------------------------
// K final: 3 CTAs/SM, 2-stage, swizzled x/w tiles (64B), a1 144B-pitch trans.
// Stage = 29696.
// ---------------------------------------------------------------------------
#define FN_STAGE 29696
#define FN_SMEM  59392

__device__ __forceinline__ void fn_load(uint32_t sb, int kc, size_t rb, int eb, int t) {
    {
        int cc2 = t >> 3, ch = t & 7;
        cp_async16(sb + cc2 * 144 + ch * 16, g_a2h + (size_t)(kc + cc2) * RR + rb + ch * 8);
        cp_async16(sb + 4608 + cc2 * 144 + ch * 16, g_a2l + (size_t)(kc + cc2) * RR + rb + ch * 8);
    }
    int r = t >> 2, ch = t & 3;
    uint32_t off = r * 64 + ((ch ^ ((r >> 1) & 3)) << 4);
    cp_async16(sb + 9216 + off, g_xh + (rb + r) * CC + kc + ch * 8);
    cp_async16(sb + 13312 + off, g_xl + (rb + r) * CC + kc + ch * 8);
    cp_async16(sb + 17408 + off, g_w1h + (size_t)(eb + r) * CC + kc + ch * 8);
    cp_async16(sb + 21504 + off, g_w1l + (size_t)(eb + r) * CC + kc + ch * 8);
    cp_async16(sb + 25600 + off, g_w2h + (size_t)(eb + r) * CC + kc + ch * 8);
}

__global__ void __launch_bounds__(256, 3) k_final_mma(const float* __restrict__ bout,
                                                      const float* __restrict__ bgo,
                                                      float* __restrict__ out) {
    extern __shared__ char smem[];
    const uint32_t sbase = smem_u32(smem);
    const int t = threadIdx.x, lane = t & 31, wid = t >> 5;
    const int eb = blockIdx.x * 64;
    const size_t rb = (size_t)blockIdx.y * 64;
    const int m0 = (wid >> 2) * 32, n0 = (wid & 3) * 16;

    float accO[2][2][4] = {}, accG[2][2][4] = {};

    const int crow = (lane & 7) + ((lane >> 4) & 1) * 8;
    const int r8 = ((lane >> 3) & 1) * 8;
    const int rA = m0 + (lane & 15);
    const int sA = (rA >> 1) & 3;
    const int cA = lane >> 4;
    const int bRow = (lane & 7) + ((lane >> 4) << 3);
    const int rB = n0 + bRow;
    const int sB = (bRow >> 1) & 3;
    const int cB = (lane >> 3) & 1;

    fn_load(sbase, 0, rb, eb, t);             CP_COMMIT();
    fn_load(sbase + FN_STAGE, 32, rb, eb, t); CP_COMMIT();

    for (int kch = 0; kch < 4; kch++) {
        CP_WAIT1();
        __syncthreads();
        const uint32_t st = sbase + (kch & 1) * FN_STAGE;
#pragma unroll
        for (int kk = 0; kk < 2; kk++) {
            const uint32_t aOff = (uint32_t)rA * 64 + (((cA ^ (kk << 1)) ^ sA) << 4);
            const uint32_t bOff = (uint32_t)rB * 64 + (((cB ^ (kk << 1)) ^ sB) << 4);
            {
                uint32_t a1h[2][4], a1l[2][4], b1h[2][2], b1l[2][2];
                const uint32_t aT = st + (kk * 16 + crow) * 144 + (m0 + r8) * 2;
#pragma unroll
                for (int mi = 0; mi < 2; mi++) {
                    ldsm4t(aT + mi * 32, a1h[mi]);
                    ldsm4t(aT + mi * 32 + 4608, a1l[mi]);
                }
                ldsm4(st + 17408 + bOff, &b1h[0][0]);
                ldsm4(st + 21504 + bOff, &b1l[0][0]);
#pragma unroll
                for (int ni = 0; ni < 2; ni++)
#pragma unroll
                    for (int mi = 0; mi < 2; mi++) mma16816(accO[mi][ni], a1h[mi], b1h[ni]);
#pragma unroll
                for (int ni = 0; ni < 2; ni++)
#pragma unroll
                    for (int mi = 0; mi < 2; mi++) mma16816(accO[mi][ni], a1l[mi], b1h[ni]);
#pragma unroll
                for (int ni = 0; ni < 2; ni++)
#pragma unroll
                    for (int mi = 0; mi < 2; mi++) mma16816(accO[mi][ni], a1h[mi], b1l[ni]);
            }
            {
                uint32_t a2h[2][4], a2l[2][4], b2h[2][2];
#pragma unroll
                for (int mi = 0; mi < 2; mi++) {
                    ldsm4(st + 9216 + aOff + mi * 1024, a2h[mi]);
                    ldsm4(st + 13312 + aOff + mi * 1024, a2l[mi]);
                }
                ldsm4(st + 25600 + bOff, &b2h[0][0]);
#pragma unroll
                for (int ni = 0; ni < 2; ni++)
#pragma unroll
                    for (int mi = 0; mi < 2; mi++) mma16816(accG[mi][ni], a2h[mi], b2h[ni]);
#pragma unroll
                for (int ni = 0; ni < 2; ni++)
#pragma unroll
                    for (int mi = 0; mi < 2; mi++) mma16816(accG[mi][ni], a2l[mi], b2h[ni]);
            }
        }
        __syncthreads();
        if (kch + 2 < 4) fn_load(sbase + (kch & 1) * FN_STAGE, (kch + 2) * 32, rb, eb, t);
        CP_COMMIT();
    }

    const int mr = lane >> 2, ncl = (lane & 3) * 2;
    float mm[2][2], rs[2][2];
#pragma unroll
    for (int mi = 0; mi < 2; mi++)
#pragma unroll
        for (int half = 0; half < 2; half++) {
            size_t r = rb + m0 + mi * 16 + mr + half * 8;
            mm[mi][half] = g_mean[r];
            rs[mi][half] = g_rstd[r];
        }
#pragma unroll
    for (int ni = 0; ni < 2; ni++) {
        int e0 = eb + n0 + ni * 8 + ncl;
        float s1a = g_S1[e0], s1b = g_S1[e0 + 1];
        float s2a = g_S2[e0], s2b = g_S2[e0 + 1];
        float boa = __ldg(bout + e0), bob = __ldg(bout + e0 + 1);
        float bga = __ldg(bgo + e0), bgb = __ldg(bgo + e0 + 1);
#pragma unroll
        for (int mi = 0; mi < 2; mi++)
#pragma unroll
            for (int half = 0; half < 2; half++) {
                size_t r = rb + m0 + mi * 16 + mr + half * 8;
                float p0 = accO[mi][ni][half * 2], p1 = accO[mi][ni][half * 2 + 1];
                float q0 = accG[mi][ni][half * 2], q1 = accG[mi][ni][half * 2 + 1];
                float o0 = (rs[mi][half] * (p0 - mm[mi][half] * s1a) + s2a + boa) * sigm(q0 + bga);
                float o1 = (rs[mi][half] * (p1 - mm[mi][half] * s1b) + s2b + bob) * sigm(q1 + bgb);
                *(float2*)(out + r * CC + e0) = make_float2(o0, o1);
            }
    }
}

// ---------------------------------------------------------------------------
extern "C" void kernel_launch(void* const* d_in, const int* in_sizes, int n_in,
                              void* d_out, int out_size) {
    const float* act   = (const float*)d_in[0];
    const float* mask  = (const float*)d_in[1];
    const float* ln_s  = (const float*)d_in[2];
    const float* ln_o  = (const float*)d_in[3];
    const float* wproj = (const float*)d_in[4];
    const float* wgate = (const float*)d_in[5];
    const float* cn_s  = (const float*)d_in[6];
    const float* cn_o  = (const float*)d_in[7];
    const float* wout  = (const float*)d_in[8];
    const float* bout  = (const float*)d_in[9];
    const float* wgo   = (const float*)d_in[10];
    const float* bgo   = (const float*)d_in[11];
    float* out = (float*)d_out;

    cudaFuncSetAttribute(k_projgate_mma, cudaFuncAttributeMaxDynamicSharedMemorySize, PG_SMEM);
    cudaFuncSetAttribute(k_pairmm_mma, cudaFuncAttributeMaxDynamicSharedMemorySize, PM_SMEM);
    cudaFuncSetAttribute(k_final_mma, cudaFuncAttributeMaxDynamicSharedMemorySize, FN_SMEM);

    k_prep_pg<<<128, 256>>>(wproj, wgate);                                  // 1
    k_prep_out<<<64, 256>>>(wout, wgo, cn_s);                               // 2
    k_layernorm<<<(int)(RR / 8), 256>>>(act, ln_s, ln_o);                   // 3
    k_projgate_mma<<<dim3(4, 4096), 256, PG_SMEM>>>(mask);                  // 4
    k_pairmm_mma<<<dim3(8, 8, 128), 256, PM_SMEM>>>();                      // 5
    k_prep_s<<<128, 128>>>(wout, cn_s, cn_o);                               // 6
    k_cstats<<<256, 256>>>();                                               // 7
    k_final_mma<<<dim3(2, 4096), 256, FN_SMEM>>>(bout, bgo, out);           // 8
}

// round 16
// speedup vs baseline: 1.0765x; 1.0263x over previous
#include <cuda_runtime.h>
#include <cuda_bf16.h>
#include <math.h>
#include <cstdint>

#define NN 512
#define CC 128
constexpr size_t RR = (size_t)NN * NN;
constexpr size_t RC = RR * CC;

__device__ __nv_bfloat16 g_xh[RC], g_xl[RC];
__device__ __nv_bfloat16 g_ah[RC], g_al[RC];
__device__ __nv_bfloat16 g_bh[RC], g_bl[RC];
__device__ __nv_bfloat16 g_a2h[RC], g_a2l[RC];
__device__ float g_mean[RR], g_rstd[RR];

__device__ __nv_bfloat16 g_wph[256 * CC], g_wpl[256 * CC];
__device__ __nv_bfloat16 g_wgh[256 * CC];
__device__ __nv_bfloat16 g_w1h[CC * CC], g_w1l[CC * CC];
__device__ __nv_bfloat16 g_w2h[CC * CC];
__device__ float g_S1[CC], g_S2[CC];

__device__ __forceinline__ float sigm(float z) { return 1.0f / (1.0f + __expf(-z)); }
__device__ __forceinline__ void split_bf16(float v, unsigned short& h, unsigned short& l) {
    __nv_bfloat16 hb = __float2bfloat16(v);
    float rem = v - __bfloat162float(hb);
    h = __bfloat16_as_ushort(hb);
    l = __bfloat16_as_ushort(__float2bfloat16(rem));
}
__device__ __forceinline__ float bf2f(uint32_t u) {
    return __bfloat162float(__ushort_as_bfloat16((unsigned short)(u & 0xffffu)));
}
__device__ __forceinline__ uint32_t smem_u32(const void* p) {
    uint32_t a;
    asm("{ .reg .u64 t; cvta.to.shared.u64 t, %1; cvt.u32.u64 %0, t; }" : "=r"(a) : "l"(p));
    return a;
}
__device__ __forceinline__ void cp_async16(uint32_t dst, const void* src) {
    asm volatile("cp.async.cg.shared.global [%0], [%1], 16;" :: "r"(dst), "l"(src));
}
#define CP_COMMIT() asm volatile("cp.async.commit_group;" ::: "memory")
#define CP_WAIT1()  asm volatile("cp.async.wait_group 1;" ::: "memory")

__device__ __forceinline__ void ldsm4(uint32_t addr, uint32_t* r) {
    asm volatile("ldmatrix.sync.aligned.m8n8.x4.shared.b16 {%0,%1,%2,%3}, [%4];"
                 : "=r"(r[0]), "=r"(r[1]), "=r"(r[2]), "=r"(r[3]) : "r"(addr));
}
__device__ __forceinline__ void ldsm4t(uint32_t addr, uint32_t* r) {
    asm volatile("ldmatrix.sync.aligned.m8n8.x4.trans.shared.b16 {%0,%1,%2,%3}, [%4];"
                 : "=r"(r[0]), "=r"(r[1]), "=r"(r[2]), "=r"(r[3]) : "r"(addr));
}
__device__ __forceinline__ void mma16816(float* d, const uint32_t* a, const uint32_t* b) {
    asm volatile("mma.sync.aligned.m16n8k16.row.col.f32.bf16.bf16.f32 "
                 "{%0,%1,%2,%3}, {%4,%5,%6,%7}, {%8,%9}, {%0,%1,%2,%3};"
                 : "+f"(d[0]), "+f"(d[1]), "+f"(d[2]), "+f"(d[3])
                 : "r"(a[0]), "r"(a[1]), "r"(a[2]), "r"(a[3]), "r"(b[0]), "r"(b[1]));
}

// ---------------------------------------------------------------------------
__global__ void k_layernorm(const float* __restrict__ act,
                            const float* __restrict__ scale,
                            const float* __restrict__ offset) {
    int warp = threadIdx.x >> 5, lane = threadIdx.x & 31;
    size_t row = (size_t)blockIdx.x * 8 + warp;
    float4 v = ((const float4*)(act + row * CC))[lane];
    float s = v.x + v.y + v.z + v.w;
    float q = v.x * v.x + v.y * v.y + v.z * v.z + v.w * v.w;
#pragma unroll
    for (int o = 16; o; o >>= 1) {
        s += __shfl_xor_sync(0xffffffffu, s, o);
        q += __shfl_xor_sync(0xffffffffu, q, o);
    }
    float m = s * (1.0f / CC);
    float rs = rsqrtf(q * (1.0f / CC) - m * m + 1e-5f);
    float4 sc = ((const float4*)scale)[lane];
    float4 of = ((const float4*)offset)[lane];
    float o[4] = {(v.x - m) * rs * sc.x + of.x, (v.y - m) * rs * sc.y + of.y,
                  (v.z - m) * rs * sc.z + of.z, (v.w - m) * rs * sc.w + of.w};
    unsigned short hs[4], ls[4];
#pragma unroll
    for (int u = 0; u < 4; u++) split_bf16(o[u], hs[u], ls[u]);
    *(uint2*)(g_xh + row * CC + lane * 4) =
        make_uint2((uint32_t)hs[0] | ((uint32_t)hs[1] << 16), (uint32_t)hs[2] | ((uint32_t)hs[3] << 16));
    *(uint2*)(g_xl + row * CC + lane * 4) =
        make_uint2((uint32_t)ls[0] | ((uint32_t)ls[1] << 16), (uint32_t)ls[2] | ((uint32_t)ls[3] << 16));
}

// ---------------------------------------------------------------------------
__global__ void k_prep_pg(const float* __restrict__ wproj, const float* __restrict__ wgate) {
    int idx = blockIdx.x * 256 + threadIdx.x;
    int d = idx >> 7, c = idx & 127;
    unsigned short h, l;
    split_bf16(wproj[(size_t)c * 256 + d], h, l);
    g_wph[idx] = __ushort_as_bfloat16(h); g_wpl[idx] = __ushort_as_bfloat16(l);
    g_wgh[idx] = __float2bfloat16(wgate[(size_t)c * 256 + d]);
}
__global__ void k_prep_out(const float* __restrict__ wout, const float* __restrict__ wgo,
                           const float* __restrict__ cs) {
    int idx = blockIdx.x * 256 + threadIdx.x;
    int e = idx >> 7, c = idx & 127;
    unsigned short h, l;
    split_bf16(cs[c] * wout[(size_t)c * CC + e], h, l);
    g_w1h[idx] = __ushort_as_bfloat16(h); g_w1l[idx] = __ushort_as_bfloat16(l);
    g_w2h[idx] = __float2bfloat16(wgo[(size_t)c * CC + e]);
}
__global__ void k_prep_s(const float* __restrict__ wout,
                         const float* __restrict__ cs, const float* __restrict__ co) {
    int e = blockIdx.x, c = threadIdx.x;
    float w = wout[(size_t)c * CC + e];
    float s1 = cs[c] * w, s2 = co[c] * w;
    __shared__ float r1[4], r2[4];
#pragma unroll
    for (int o = 16; o; o >>= 1) {
        s1 += __shfl_xor_sync(0xffffffffu, s1, o);
        s2 += __shfl_xor_sync(0xffffffffu, s2, o);
    }
    if ((c & 31) == 0) { r1[c >> 5] = s1; r2[c >> 5] = s2; }
    __syncthreads();
    if (c == 0) {
        g_S1[e] = r1[0] + r1[1] + r1[2] + r1[3];
        g_S2[e] = r2[0] + r2[1] + r2[2] + r2[3];
    }
}

// ---------------------------------------------------------------------------
// K projgate: 3 CTAs/SM, 64r x 64d dual-GEMM. Resident weights (48 KB, loaded
// once), x tiles in 3-stage rotating pipeline (8 KB/stage).
// Layout: x stages [0, 24576), wph 24576 (4x4096), wpl 40960, wgh 57344.
// ---------------------------------------------------------------------------
#define PG_XSTAGE 8192
#define PG_W      24576
#define PG_SMEM   73728

__device__ __forceinline__ void pg_loadx(uint32_t sb, int kc, size_t rb, int t) {
    int r = t >> 2, ch = t & 3;
    uint32_t off = r * 64 + ((ch ^ ((r >> 1) & 3)) << 4);
    cp_async16(sb + off, g_xh + (rb + r) * CC + kc + ch * 8);
    cp_async16(sb + 4096 + off, g_xl + (rb + r) * CC + kc + ch * 8);
}

__global__ void __launch_bounds__(256, 3) k_projgate_mma(const float* __restrict__ mask) {
    extern __shared__ char smem[];
    const uint32_t sbase = smem_u32(smem);
    const int t = threadIdx.x, lane = t & 31, wid = t >> 5;
    const int db = blockIdx.x * 64;
    const size_t rb = (size_t)blockIdx.y * 64;
    const int m0 = (wid >> 2) * 32, n0 = (wid & 3) * 16;

    float accP[2][2][4] = {}, accG[2][2][4] = {};

    const int rA = m0 + (lane & 15);
    const int sA = (rA >> 1) & 3;
    const int cA = lane >> 4;
    const int bRow = (lane & 7) + ((lane >> 4) << 3);
    const int rB = n0 + bRow;
    const int sB = (bRow >> 1) & 3;
    const int cB = (lane >> 3) & 1;

    // Resident weight load (all 4 K-chunks) + x stage 0 in one group
    {
        int r = t >> 2, ch = t & 3;
        uint32_t off = r * 64 + ((ch ^ ((r >> 1) & 3)) << 4);
#pragma unroll
        for (int c4 = 0; c4 < 4; c4++) {
            const __nv_bfloat16* wp = g_wph + (size_t)(db + r) * CC + c4 * 32 + ch * 8;
            const __nv_bfloat16* wl = g_wpl + (size_t)(db + r) * CC + c4 * 32 + ch * 8;
            const __nv_bfloat16* wg = g_wgh + (size_t)(db + r) * CC + c4 * 32 + ch * 8;
            cp_async16(sbase + PG_W + c4 * 4096 + off, wp);
            cp_async16(sbase + PG_W + 16384 + c4 * 4096 + off, wl);
            cp_async16(sbase + PG_W + 32768 + c4 * 4096 + off, wg);
        }
    }
    pg_loadx(sbase, 0, rb, t);               CP_COMMIT();
    pg_loadx(sbase + PG_XSTAGE, 32, rb, t);  CP_COMMIT();

    for (int kch = 0; kch < 4; kch++) {
        CP_WAIT1();
        __syncthreads();
        if (kch + 2 < 4)
            pg_loadx(sbase + ((kch + 2) % 3) * PG_XSTAGE, (kch + 2) * 32, rb, t);
        CP_COMMIT();
        const uint32_t sx = sbase + (kch % 3) * PG_XSTAGE;
        const uint32_t sw = sbase + PG_W + kch * 4096;
#pragma unroll
        for (int kk = 0; kk < 2; kk++) {
            const uint32_t aOff = (uint32_t)rA * 64 + (((cA ^ (kk << 1)) ^ sA) << 4);
            const uint32_t bOff = (uint32_t)rB * 64 + (((cB ^ (kk << 1)) ^ sB) << 4);
            uint32_t ah[2][4], al[2][4], b0[2][2], b1[2][2];
#pragma unroll
            for (int mi = 0; mi < 2; mi++) {
                ldsm4(sx + aOff + mi * 1024, ah[mi]);
                ldsm4(sx + 4096 + aOff + mi * 1024, al[mi]);
            }
            ldsm4(sw + bOff, &b0[0][0]);
            ldsm4(sw + 16384 + bOff, &b1[0][0]);
#pragma unroll
            for (int ni = 0; ni < 2; ni++)
#pragma unroll
                for (int mi = 0; mi < 2; mi++) mma16816(accP[mi][ni], ah[mi], b0[ni]);
#pragma unroll
            for (int ni = 0; ni < 2; ni++)
#pragma unroll
                for (int mi = 0; mi < 2; mi++) mma16816(accP[mi][ni], al[mi], b0[ni]);
#pragma unroll
            for (int ni = 0; ni < 2; ni++)
#pragma unroll
                for (int mi = 0; mi < 2; mi++) mma16816(accP[mi][ni], ah[mi], b1[ni]);
            ldsm4(sw + 32768 + bOff, &b0[0][0]);
#pragma unroll
            for (int ni = 0; ni < 2; ni++)
#pragma unroll
                for (int mi = 0; mi < 2; mi++) mma16816(accG[mi][ni], ah[mi], b0[ni]);
#pragma unroll
            for (int ni = 0; ni < 2; ni++)
#pragma unroll
                for (int mi = 0; mi < 2; mi++) mma16816(accG[mi][ni], al[mi], b0[ni]);
        }
    }
    __syncthreads();

    float* buf = (float*)smem;
    const int mr = lane >> 2, ncq = lane & 3;
#pragma unroll
    for (int mi = 0; mi < 2; mi++) {
        int rl = m0 + mi * 16 + mr;
        float mk0 = __ldg(mask + rb + rl), mk8 = __ldg(mask + rb + rl + 8);
#pragma unroll
        for (int ni = 0; ni < 2; ni++) {
            int d0 = n0 + ni * 8 + ncq * 2;
            buf[d0 * 68 + rl]           = accP[mi][ni][0] * sigm(accG[mi][ni][0]) * mk0;
            buf[(d0 + 1) * 68 + rl]     = accP[mi][ni][1] * sigm(accG[mi][ni][1]) * mk0;
            buf[d0 * 68 + rl + 8]       = accP[mi][ni][2] * sigm(accG[mi][ni][2]) * mk8;
            buf[(d0 + 1) * 68 + rl + 8] = accP[mi][ni][3] * sigm(accG[mi][ni][3]) * mk8;
        }
    }
    __syncthreads();

    {
        int dl = t >> 2, rg = t & 3;
        int dg = db + dl, c = dg >> 1;
        __nv_bfloat16* dsth = (dg & 1) ? g_bh : g_ah;
        __nv_bfloat16* dstl = (dg & 1) ? g_bl : g_al;
        size_t base = (size_t)c * RR + rb + rg * 16;
#pragma unroll
        for (int i4 = 0; i4 < 2; i4++) {
            float4 va = *(float4*)&buf[dl * 68 + rg * 16 + i4 * 8];
            float4 vb = *(float4*)&buf[dl * 68 + rg * 16 + i4 * 8 + 4];
            float vv[8] = {va.x, va.y, va.z, va.w, vb.x, vb.y, vb.z, vb.w};
            unsigned short hs[8], ls[8];
#pragma unroll
            for (int j = 0; j < 8; j++) split_bf16(vv[j], hs[j], ls[j]);
            *(uint4*)(dsth + base + i4 * 8) =
                make_uint4((uint32_t)hs[0] | ((uint32_t)hs[1] << 16), (uint32_t)hs[2] | ((uint32_t)hs[3] << 16),
                           (uint32_t)hs[4] | ((uint32_t)hs[5] << 16), (uint32_t)hs[6] | ((uint32_t)hs[7] << 16));
            *(uint4*)(dstl + base + i4 * 8) =
                make_uint4((uint32_t)ls[0] | ((uint32_t)ls[1] << 16), (uint32_t)ls[2] | ((uint32_t)ls[3] << 16),
                           (uint32_t)ls[4] | ((uint32_t)ls[5] << 16), (uint32_t)ls[6] | ((uint32_t)ls[7] << 16));
        }
    }
}

// ---------------------------------------------------------------------------
// K pairmm: unchanged R13/R15 (3-stage, 4 CTAs/SM, swizzled).
// ---------------------------------------------------------------------------
#define PM_STAGE 16384
#define PM_SMEM  49152

__device__ __forceinline__ void pm_load(uint32_t sb, int kc, size_t cOff, int ib, int jb, int t) {
    int r = t >> 2, ch = t & 3;
    uint32_t off = r * 64 + ((ch ^ ((r >> 1) & 3)) << 4);
    cp_async16(sb + off, g_ah + cOff + (size_t)(ib + r) * NN + kc + ch * 8);
    cp_async16(sb + 4096 + off, g_al + cOff + (size_t)(ib + r) * NN + kc + ch * 8);
    cp_async16(sb + 8192 + off, g_bh + cOff + (size_t)(jb + r) * NN + kc + ch * 8);
    cp_async16(sb + 12288 + off, g_bl + cOff + (size_t)(jb + r) * NN + kc + ch * 8);
}

__global__ void __launch_bounds__(256, 4) k_pairmm_mma() {
    extern __shared__ char smem[];
    const uint32_t sbase = smem_u32(smem);
    const int t = threadIdx.x, lane = t & 31, wid = t >> 5;
    const int c = blockIdx.z;
    const int ib = blockIdx.y * 64, jb = blockIdx.x * 64;
    const size_t cOff = (size_t)c * RR;
    const int m0 = (wid >> 2) * 32, n0 = (wid & 3) * 16;

    float acc[2][2][4] = {};

    const int rA = m0 + (lane & 15);
    const int sA = (rA >> 1) & 3;
    const int cA = lane >> 4;
    const int bRow = (lane & 7) + ((lane >> 4) << 3);
    const int rB = n0 + bRow;
    const int sB = (bRow >> 1) & 3;
    const int cB = (lane >> 3) & 1;

    pm_load(sbase, 0, cOff, ib, jb, t);             CP_COMMIT();
    pm_load(sbase + PM_STAGE, 32, cOff, ib, jb, t); CP_COMMIT();

    for (int kch = 0; kch < 16; kch++) {
        CP_WAIT1();
        __syncthreads();
        if (kch + 2 < 16)
            pm_load(sbase + ((kch + 2) % 3) * PM_STAGE, (kch + 2) * 32, cOff, ib, jb, t);
        CP_COMMIT();
        const uint32_t sb = sbase + (kch % 3) * PM_STAGE;
#pragma unroll
        for (int kk = 0; kk < 2; kk++) {
            const uint32_t aOff = (uint32_t)rA * 64 + (((cA ^ (kk << 1)) ^ sA) << 4);
            const uint32_t bOff = (uint32_t)rB * 64 + (((cB ^ (kk << 1)) ^ sB) << 4);
            uint32_t ah[2][4], al[2][4], bh[2][2], bl[2][2];
#pragma unroll
            for (int mi = 0; mi < 2; mi++) {
                ldsm4(sb + aOff + mi * 1024, ah[mi]);
                ldsm4(sb + 4096 + aOff + mi * 1024, al[mi]);
            }
            ldsm4(sb + 8192 + bOff, &bh[0][0]);
            ldsm4(sb + 12288 + bOff, &bl[0][0]);
#pragma unroll
            for (int ni = 0; ni < 2; ni++)
#pragma unroll
                for (int mi = 0; mi < 2; mi++) mma16816(acc[mi][ni], ah[mi], bh[ni]);
#pragma unroll
            for (int ni = 0; ni < 2; ni++)
#pragma unroll
                for (int mi = 0; mi < 2; mi++) mma16816(acc[mi][ni], al[mi], bh[ni]);
#pragma unroll
            for (int ni = 0; ni < 2; ni++)
#pragma unroll
                for (int mi = 0; mi < 2; mi++) mma16816(acc[mi][ni], ah[mi], bl[ni]);
        }
    }

    const int mr = lane >> 2, nc = (lane & 3) * 2;
#pragma unroll
    for (int mi = 0; mi < 2; mi++)
#pragma unroll
        for (int ni = 0; ni < 2; ni++) {
            size_t pos0 = cOff + (size_t)(ib + m0 + mi * 16 + mr) * NN + jb + n0 + ni * 8 + nc;
            size_t pos8 = pos0 + (size_t)8 * NN;
            unsigned short h0, l0, h1, l1;
            split_bf16(acc[mi][ni][0], h0, l0); split_bf16(acc[mi][ni][1], h1, l1);
            *(uint32_t*)(g_a2h + pos0) = (uint32_t)h0 | ((uint32_t)h1 << 16);
            *(uint32_t*)(g_a2l + pos0) = (uint32_t)l0 | ((uint32_t)l1 << 16);
            split_bf16(acc[mi][ni][2], h0, l0); split_bf16(acc[mi][ni][3], h1, l1);
            *(uint32_t*)(g_a2h + pos8) = (uint32_t)h0 | ((uint32_t)h1 << 16);
            *(uint32_t*)(g_a2l + pos8) = (uint32_t)l0 | ((uint32_t)l1 << 16);
        }
}

// ---------------------------------------------------------------------------
__global__ void k_cstats() {
    size_t r0 = ((size_t)blockIdx.x * 256 + threadIdx.x) * 4;
    float s[4] = {}, q[4] = {};
#pragma unroll 4
    for (int c = 0; c < CC; c++) {
        uint2 hv = *(const uint2*)(g_a2h + (size_t)c * RR + r0);
        uint2 lv = *(const uint2*)(g_a2l + (size_t)c * RR + r0);
        float v[4] = {bf2f(hv.x) + bf2f(lv.x), bf2f(hv.x >> 16) + bf2f(lv.x >> 16),
                      bf2f(hv.y) + bf2f(lv.y), bf2f(hv.y >> 16) + bf2f(lv.y >> 16)};
#pragma unroll
        for (int j = 0; j < 4; j++) { s[j] += v[j]; q[j] += v[j] * v[j]; }
    }
    float4 mo, ro;
    float* mp = &mo.x; float* rp = &ro.x;
#pragma unroll
    for (int j = 0; j < 4; j++) {
        float m = s[j] * (1.0f / CC);
        mp[j] = m;
        rp[j] = rsqrtf(q[j] * (1.0f / CC) - m * m + 1e-5f);
    }
    *(float4*)(g_mean + r0) = mo;
    *(float4*)(g_rstd + r0) = ro;
}

// ---------------------------------------------------------------------------
// K final: unchanged R15 (3 CTAs/SM, 2-stage, swizzled x/w, a1 144B trans).
// ---------------------------------------------------------------------------
#define FN_STAGE 29696
#define FN_SMEM  59392

__device__ __forceinline__ void fn_load(uint32_t sb, int kc, size_t rb, int eb, int t) {
    {
        int cc2 = t >> 3, ch = t & 7;
        cp_async16(sb + cc2 * 144 + ch * 16, g_a2h + (size_t)(kc + cc2) * RR + rb + ch * 8);
        cp_async16(sb + 4608 + cc2 * 144 + ch * 16, g_a2l + (size_t)(kc + cc2) * RR + rb + ch * 8);
    }
    int r = t >> 2, ch = t & 3;
    uint32_t off = r * 64 + ((ch ^ ((r >> 1) & 3)) << 4);
    cp_async16(sb + 9216 + off, g_xh + (rb + r) * CC + kc + ch * 8);
    cp_async16(sb + 13312 + off, g_xl + (rb + r) * CC + kc + ch * 8);
    cp_async16(sb + 17408 + off, g_w1h + (size_t)(eb + r) * CC + kc + ch * 8);
    cp_async16(sb + 21504 + off, g_w1l + (size_t)(eb + r) * CC + kc + ch * 8);
    cp_async16(sb + 25600 + off, g_w2h + (size_t)(eb + r) * CC + kc + ch * 8);
}

__global__ void __launch_bounds__(256, 3) k_final_mma(const float* __restrict__ bout,
                                                      const float* __restrict__ bgo,
                                                      float* __restrict__ out) {
    extern __shared__ char smem[];
    const uint32_t sbase = smem_u32(smem);
    const int t = threadIdx.x, lane = t & 31, wid = t >> 5;
    const int eb = blockIdx.x * 64;
    const size_t rb = (size_t)blockIdx.y * 64;
    const int m0 = (wid >> 2) * 32, n0 = (wid & 3) * 16;

    float accO[2][2][4] = {}, accG[2][2][4] = {};

    const int crow = (lane & 7) + ((lane >> 4) & 1) * 8;
    const int r8 = ((lane >> 3) & 1) * 8;
    const int rA = m0 + (lane & 15);
    const int sA = (rA >> 1) & 3;
    const int cA = lane >> 4;
    const int bRow = (lane & 7) + ((lane >> 4) << 3);
    const int rB = n0 + bRow;
    const int sB = (bRow >> 1) & 3;
    const int cB = (lane >> 3) & 1;

    fn_load(sbase, 0, rb, eb, t);             CP_COMMIT();
    fn_load(sbase + FN_STAGE, 32, rb, eb, t); CP_COMMIT();

    for (int kch = 0; kch < 4; kch++) {
        CP_WAIT1();
        __syncthreads();
        const uint32_t st = sbase + (kch & 1) * FN_STAGE;
#pragma unroll
        for (int kk = 0; kk < 2; kk++) {
            const uint32_t aOff = (uint32_t)rA * 64 + (((cA ^ (kk << 1)) ^ sA) << 4);
            const uint32_t bOff = (uint32_t)rB * 64 + (((cB ^ (kk << 1)) ^ sB) << 4);
            {
                uint32_t a1h[2][4], a1l[2][4], b1h[2][2], b1l[2][2];
                const uint32_t aT = st + (kk * 16 + crow) * 144 + (m0 + r8) * 2;
#pragma unroll
                for (int mi = 0; mi < 2; mi++) {
                    ldsm4t(aT + mi * 32, a1h[mi]);
                    ldsm4t(aT + mi * 32 + 4608, a1l[mi]);
                }
                ldsm4(st + 17408 + bOff, &b1h[0][0]);
                ldsm4(st + 21504 + bOff, &b1l[0][0]);
#pragma unroll
                for (int ni = 0; ni < 2; ni++)
#pragma unroll
                    for (int mi = 0; mi < 2; mi++) mma16816(accO[mi][ni], a1h[mi], b1h[ni]);
#pragma unroll
                for (int ni = 0; ni < 2; ni++)
#pragma unroll
                    for (int mi = 0; mi < 2; mi++) mma16816(accO[mi][ni], a1l[mi], b1h[ni]);
#pragma unroll
                for (int ni = 0; ni < 2; ni++)
#pragma unroll
                    for (int mi = 0; mi < 2; mi++) mma16816(accO[mi][ni], a1h[mi], b1l[ni]);
            }
            {
                uint32_t a2h[2][4], a2l[2][4], b2h[2][2];
#pragma unroll
                for (int mi = 0; mi < 2; mi++) {
                    ldsm4(st + 9216 + aOff + mi * 1024, a2h[mi]);
                    ldsm4(st + 13312 + aOff + mi * 1024, a2l[mi]);
                }
                ldsm4(st + 25600 + bOff, &b2h[0][0]);
#pragma unroll
                for (int ni = 0; ni < 2; ni++)
#pragma unroll
                    for (int mi = 0; mi < 2; mi++) mma16816(accG[mi][ni], a2h[mi], b2h[ni]);
#pragma unroll
                for (int ni = 0; ni < 2; ni++)
#pragma unroll
                    for (int mi = 0; mi < 2; mi++) mma16816(accG[mi][ni], a2l[mi], b2h[ni]);
            }
        }
        __syncthreads();
        if (kch + 2 < 4) fn_load(sbase + (kch & 1) * FN_STAGE, (kch + 2) * 32, rb, eb, t);
        CP_COMMIT();
    }

    const int mr = lane >> 2, ncl = (lane & 3) * 2;
    float mm[2][2], rs[2][2];
#pragma unroll
    for (int mi = 0; mi < 2; mi++)
#pragma unroll
        for (int half = 0; half < 2; half++) {
            size_t r = rb + m0 + mi * 16 + mr + half * 8;
            mm[mi][half] = g_mean[r];
            rs[mi][half] = g_rstd[r];
        }
#pragma unroll
    for (int ni = 0; ni < 2; ni++) {
        int e0 = eb + n0 + ni * 8 + ncl;
        float s1a = g_S1[e0], s1b = g_S1[e0 + 1];
        float s2a = g_S2[e0], s2b = g_S2[e0 + 1];
        float boa = __ldg(bout + e0), bob = __ldg(bout + e0 + 1);
        float bga = __ldg(bgo + e0), bgb = __ldg(bgo + e0 + 1);
#pragma unroll
        for (int mi = 0; mi < 2; mi++)
#pragma unroll
            for (int half = 0; half < 2; half++) {
                size_t r = rb + m0 + mi * 16 + mr + half * 8;
                float p0 = accO[mi][ni][half * 2], p1 = accO[mi][ni][half * 2 + 1];
                float q0 = accG[mi][ni][half * 2], q1 = accG[mi][ni][half * 2 + 1];
                float o0 = (rs[mi][half] * (p0 - mm[mi][half] * s1a) + s2a + boa) * sigm(q0 + bga);
                float o1 = (rs[mi][half] * (p1 - mm[mi][half] * s1b) + s2b + bob) * sigm(q1 + bgb);
                *(float2*)(out + r * CC + e0) = make_float2(o0, o1);
            }
    }
}

// ---------------------------------------------------------------------------
extern "C" void kernel_launch(void* const* d_in, const int* in_sizes, int n_in,
                              void* d_out, int out_size) {
    const float* act   = (const float*)d_in[0];
    const float* mask  = (const float*)d_in[1];
    const float* ln_s  = (const float*)d_in[2];
    const float* ln_o  = (const float*)d_in[3];
    const float* wproj = (const float*)d_in[4];
    const float* wgate = (const float*)d_in[5];
    const float* cn_s  = (const float*)d_in[6];
    const float* cn_o  = (const float*)d_in[7];
    const float* wout  = (const float*)d_in[8];
    const float* bout  = (const float*)d_in[9];
    const float* wgo   = (const float*)d_in[10];
    const float* bgo   = (const float*)d_in[11];
    float* out = (float*)d_out;

    cudaFuncSetAttribute(k_projgate_mma, cudaFuncAttributeMaxDynamicSharedMemorySize, PG_SMEM);
    cudaFuncSetAttribute(k_pairmm_mma, cudaFuncAttributeMaxDynamicSharedMemorySize, PM_SMEM);
    cudaFuncSetAttribute(k_final_mma, cudaFuncAttributeMaxDynamicSharedMemorySize, FN_SMEM);

    k_prep_pg<<<128, 256>>>(wproj, wgate);                                  // 1
    k_prep_out<<<64, 256>>>(wout, wgo, cn_s);                               // 2
    k_layernorm<<<(int)(RR / 8), 256>>>(act, ln_s, ln_o);                   // 3
    k_projgate_mma<<<dim3(4, 4096), 256, PG_SMEM>>>(mask);                  // 4 <- profiled
    k_pairmm_mma<<<dim3(8, 8, 128), 256, PM_SMEM>>>();                      // 5
    k_prep_s<<<128, 128>>>(wout, cn_s, cn_o);                               // 6
    k_cstats<<<256, 256>>>();                                               // 7
    k_final_mma<<<dim3(2, 4096), 256, FN_SMEM>>>(bout, bgo, out);           // 8
}